// round 11
// baseline (speedup 1.0000x reference)
#include <cuda_runtime.h>
#include <cuda_fp16.h>

#define NN   50000
#define EE   800000
#define HID  64
#define IND  128
#define OUTD 40
#define NBLK ((NN + 255) / 256)   // 196
#define GB   ((NN + 63) / 64)     // 782
#define HB   ((EE + 255) / 256)   // 3125
#define WTOT (IND*64 + HID*64 + HID*64 + 192*64)

// ---------------- device scratch ----------------
__device__ __half g_hlinA[NN * HID];
__device__ __half g_hlinB[NN * HID];
__device__ __half g_h0[NN * HID];
__device__ __half g_h1[NN * HID];
__device__ __half g_w1[IND * 64];
__device__ __half g_w2[HID * 64];
__device__ __half g_w3[HID * 64];
__device__ __half g_wl[192 * 64];
__device__ int   g_rowptr[NN + 1];
__device__ int   g_cnt[NN];
__device__ int   g_rank[EE];
__device__ int   g_agg[NBLK];
__device__ int   g_flag[NBLK];
__device__ int4  g_edge4[EE / 2];
__device__ int   g_is64;

__device__ __forceinline__ int clampN(int v) {
    return (v < 0) ? 0 : ((v >= NN) ? NN - 1 : v);
}
__device__ __forceinline__ int edge_at(const int* __restrict__ p32, int row, int e, int is64) {
    long long idx = (long long)row * EE + e;
    return is64 ? p32[2 * idx] : p32[idx];
}
__device__ __forceinline__ unsigned smem_u32(const void* p) {
    return (unsigned)__cvta_generic_to_shared(p);
}
__device__ __forceinline__ void ldm_x4(unsigned& r0, unsigned& r1, unsigned& r2, unsigned& r3, unsigned a) {
    asm volatile("ldmatrix.sync.aligned.m8n8.x4.shared.b16 {%0,%1,%2,%3}, [%4];"
                 : "=r"(r0), "=r"(r1), "=r"(r2), "=r"(r3) : "r"(a));
}
__device__ __forceinline__ void ldm_x4_t(unsigned& r0, unsigned& r1, unsigned& r2, unsigned& r3, unsigned a) {
    asm volatile("ldmatrix.sync.aligned.m8n8.x4.trans.shared.b16 {%0,%1,%2,%3}, [%4];"
                 : "=r"(r0), "=r"(r1), "=r"(r2), "=r"(r3) : "r"(a));
}
__device__ __forceinline__ void mma16816(float* c, unsigned a0, unsigned a1, unsigned a2, unsigned a3,
                                         unsigned b0, unsigned b1) {
    asm volatile("mma.sync.aligned.m16n8k16.row.col.f32.f16.f16.f32 "
                 "{%0,%1,%2,%3}, {%4,%5,%6,%7}, {%8,%9}, {%0,%1,%2,%3};"
                 : "+f"(c[0]), "+f"(c[1]), "+f"(c[2]), "+f"(c[3])
                 : "r"(a0), "r"(a1), "r"(a2), "r"(a3), "r"(b0), "r"(b1));
}

// ---------------- prep: weights fp32->fp16, zero counters/flags, dtype detect ----------------
__global__ void prepw_zero_kernel(const float* __restrict__ W1,
                                  const float* __restrict__ W2,
                                  const float* __restrict__ W3,
                                  const float* __restrict__ Wl,
                                  const int* __restrict__ p32) {
    int i = blockIdx.x * 256 + threadIdx.x;
    if (i < NN) g_cnt[i] = 0;
    if (i < NBLK) g_flag[i] = 0;
    if (i < WTOT) {
        int j = i;
        if (j < IND * 64) { g_w1[j] = __float2half_rn(W1[j]); }
        else {
            j -= IND * 64;
            if (j < HID * 64) { g_w2[j] = __float2half_rn(W2[j]); }
            else {
                j -= HID * 64;
                if (j < HID * 64) { g_w3[j] = __float2half_rn(W3[j]); }
                else {
                    j -= HID * 64;
                    int k = j >> 6, c = j & 63;
                    g_wl[j] = (c < OUTD) ? __float2half_rn(Wl[k * OUTD + c]) : __float2half_rn(0.f);
                }
            }
        }
    }
    if (blockIdx.x == 0 && threadIdx.x < 32) {
        int lane = threadIdx.x;
        int any = p32[2 * lane + 1] | p32[2 * (lane + 32) + 1];
        unsigned nz = __ballot_sync(0xFFFFFFFFu, any != 0);
        if (lane == 0) g_is64 = (nz == 0) ? 1 : 0;
    }
}

// ---------------- histogram + rank capture ----------------
__global__ void hist_kernel(const int* __restrict__ ei32) {
    int e = blockIdx.x * blockDim.x + threadIdx.x;
    if (e < EE) {
        int d = clampN(edge_at(ei32, 1, e, g_is64));
        g_rank[e] = atomicAdd(&g_cnt[d], 1);
    }
}

// ---------------- single-pass scan ----------------
__device__ __forceinline__ int block_excl_scan_256(int v, int tid, int* wsum) {
    int lane = tid & 31, w = tid >> 5;
    int x = v;
#pragma unroll
    for (int o = 1; o < 32; o <<= 1) {
        int y = __shfl_up_sync(0xFFFFFFFFu, x, o);
        if (lane >= o) x += y;
    }
    if (lane == 31) wsum[w] = x;
    __syncthreads();
    if (w == 0) {
        int s = (lane < 8) ? wsum[lane] : 0;
#pragma unroll
        for (int o = 1; o < 8; o <<= 1) {
            int y = __shfl_up_sync(0xFFFFFFFFu, s, o);
            if (lane >= o) s += y;
        }
        if (lane < 8) wsum[lane] = s;
    }
    __syncthreads();
    int incl = x + ((w > 0) ? wsum[w - 1] : 0);
    return incl - v;
}

__global__ void __launch_bounds__(256) scan_kernel() {
    __shared__ int wsum[8];
    __shared__ int s_off;
    int tid = threadIdx.x, b = blockIdx.x;

    int i = b * 256 + tid;
    int c = (i < NN) ? g_cnt[i] : 0;
    int excl = block_excl_scan_256(c, tid, wsum);
    int total = wsum[7];

    if (tid == 0) {
        g_agg[b] = total;
        __threadfence();
        *(volatile int*)&g_flag[b] = 1;
    }
    if (tid < 32) {
        int sum = 0;
        for (int p = tid; p < b; p += 32) {
            while (*(volatile int*)&g_flag[p] == 0) { }
            sum += *(volatile int*)&g_agg[p];
        }
#pragma unroll
        for (int o = 16; o > 0; o >>= 1) sum += __shfl_down_sync(0xFFFFFFFFu, sum, o);
        if (tid == 0) s_off = sum;
    }
    __syncthreads();
    int off = s_off;

    if (i < NN) g_rowptr[i] = off + excl;
    if (b == NBLK - 1 && tid == 0) g_rowptr[NN] = off + total;
}

// ---------------- fill: atomic-free scatter ----------------
__global__ void fill_kernel(const int* __restrict__ ei32,
                            const float* __restrict__ ew) {
    int e = blockIdx.x * blockDim.x + threadIdx.x;
    if (e < EE) {
        int is64 = g_is64;
        int d = clampN(edge_at(ei32, 1, e, is64));
        int s = clampN(edge_at(ei32, 0, e, is64));
        int pos = g_rowptr[d] + g_rank[e];
        ((int2*)g_edge4)[pos] = make_int2(s, __float_as_int(ew[e]));
    }
}

// ---------------- per-node aggregation helper (lane owns half2 column) ----------------
__device__ __forceinline__ __half2 agg_node(const __half2* __restrict__ hl,
                                            int node, int lane, float b0, float b1) {
    const int2* ed = (const int2*)g_edge4;
    int beg = g_rowptr[node], end = g_rowptr[node + 1];
    float a0 = 0.f, a1 = 0.f, c0 = 0.f, c1 = 0.f;
    int e = beg;
    if ((e & 1) && e < end) {
        int2 E = ed[e];
        float2 h = __half22float2(hl[(size_t)E.x * 32 + lane]);
        float w = __int_as_float(E.y);
        a0 = fmaf(w, h.x, a0); a1 = fmaf(w, h.y, a1);
        e++;
    }
    for (; e + 4 <= end; e += 4) {
        int4 Ea = g_edge4[e >> 1];
        int4 Eb = g_edge4[(e >> 1) + 1];
        float2 h0 = __half22float2(hl[(size_t)Ea.x * 32 + lane]);
        float2 h1 = __half22float2(hl[(size_t)Ea.z * 32 + lane]);
        float2 h2 = __half22float2(hl[(size_t)Eb.x * 32 + lane]);
        float2 h3 = __half22float2(hl[(size_t)Eb.z * 32 + lane]);
        float w0 = __int_as_float(Ea.y), w1 = __int_as_float(Ea.w);
        float w2 = __int_as_float(Eb.y), w3 = __int_as_float(Eb.w);
        a0 = fmaf(w0, h0.x, a0); a1 = fmaf(w0, h0.y, a1);
        c0 = fmaf(w1, h1.x, c0); c1 = fmaf(w1, h1.y, c1);
        a0 = fmaf(w2, h2.x, a0); a1 = fmaf(w2, h2.y, a1);
        c0 = fmaf(w3, h3.x, c0); c1 = fmaf(w3, h3.y, c1);
    }
    if (e + 2 <= end) {
        int4 Ea = g_edge4[e >> 1];
        float2 h0 = __half22float2(hl[(size_t)Ea.x * 32 + lane]);
        float2 h1 = __half22float2(hl[(size_t)Ea.z * 32 + lane]);
        float w0 = __int_as_float(Ea.y), w1 = __int_as_float(Ea.w);
        a0 = fmaf(w0, h0.x, a0); a1 = fmaf(w0, h0.y, a1);
        c0 = fmaf(w1, h1.x, c0); c1 = fmaf(w1, h1.y, c1);
        e += 2;
    }
    if (e < end) {
        int2 E = ed[e];
        float2 h = __half22float2(hl[(size_t)E.x * 32 + lane]);
        float w = __int_as_float(E.y);
        a0 = fmaf(w, h.x, a0); a1 = fmaf(w, h.y, a1);
    }
    a0 += c0; a1 += c1;
    return __floats2half2_rn(fmaxf(a0 + b0, 0.f), fmaxf(a1 + b1, 0.f));
}

// ---------------- gemm layer 1: x fp32 -> hlinA (tensor cores, 128 thr) ----------------
__global__ void __launch_bounds__(128) gemm1_mma_kernel(const float* __restrict__ x) {
    constexpr int K = IND;
    constexpr int XS = K + 8;
    __shared__ __half Xs[64 * XS];
    __shared__ __half Ws[K * 72];

    int tid = threadIdx.x, warp = tid >> 5, lane = tid & 31;
    int row0 = blockIdx.x * 64;

    constexpr int NF4 = K / 4;
    for (int i = tid; i < 64 * NF4; i += 128) {
        int r = i / NF4, c = i % NF4;
        int gr = row0 + r; if (gr >= NN) gr = NN - 1;
        float4 v = *(const float4*)&x[(size_t)gr * K + c * 4];
        __half2 h01 = __floats2half2_rn(v.x, v.y);
        __half2 h23 = __floats2half2_rn(v.z, v.w);
        uint2 pk; pk.x = *(unsigned*)&h01; pk.y = *(unsigned*)&h23;
        *(uint2*)&Xs[r * XS + c * 4] = pk;
    }
    for (int i = tid; i < K * 8; i += 128) {
        int r = i >> 3, c = i & 7;
        *(uint4*)&Ws[r * 72 + c * 8] = *(const uint4*)&g_w1[r * 64 + c * 8];
    }
    __syncthreads();

    int wr = warp * 16;
    float acc[8][4];
#pragma unroll
    for (int g = 0; g < 8; g++) { acc[g][0] = acc[g][1] = acc[g][2] = acc[g][3] = 0.f; }

    unsigned xb = smem_u32(Xs), wb = smem_u32(Ws);
    int arow = wr + ((lane >> 3) & 1) * 8 + (lane & 7);
    int acol8 = (lane >> 4) * 8;
    int brow8 = ((lane >> 3) & 1) * 8 + (lane & 7);

#pragma unroll
    for (int kk = 0; kk < K / 16; kk++) {
        unsigned a0, a1, a2, a3;
        ldm_x4(a0, a1, a2, a3, xb + (arow * XS + kk * 16 + acol8) * 2);
#pragma unroll
        for (int jn = 0; jn < 4; jn++) {
            unsigned b0, b1, b2, b3;
            ldm_x4_t(b0, b1, b2, b3, wb + ((kk * 16 + brow8) * 72 + jn * 16 + acol8) * 2);
            mma16816(acc[jn * 2 + 0], a0, a1, a2, a3, b0, b1);
            mma16816(acc[jn * 2 + 1], a0, a1, a2, a3, b2, b3);
        }
    }

    __half2* hl = (__half2*)g_hlinA;
    int g = lane >> 2, q = lane & 3;
#pragma unroll
    for (int gn = 0; gn < 8; gn++) {
        int r0 = row0 + wr + g, r1 = r0 + 8;
        int cidx = gn * 4 + q;
        if (r0 < NN) hl[(size_t)r0 * 32 + cidx] = __floats2half2_rn(acc[gn][0], acc[gn][1]);
        if (r1 < NN) hl[(size_t)r1 * 32 + cidx] = __floats2half2_rn(acc[gn][2], acc[gn][3]);
    }
}

// ---------------- fused agg + gemm (layers 2,3): 256 thr, 8 warps ----------------
// agg: hl_src -> (h_keep global, Xs smem), then gemm Xs @ W -> hl_dst
__global__ void __launch_bounds__(256) agg_gemm_kernel(int src_is_B,
                                                       const float* __restrict__ bias,
                                                       int keep_sel,       // 0 -> g_h0, 1 -> g_h1
                                                       int w_is_3) {
    constexpr int XS = 72;
    __shared__ __half Xs[64 * XS];
    __shared__ __half Ws[64 * 72];

    int tid = threadIdx.x, warp = tid >> 5, lane = tid & 31;
    int row0 = blockIdx.x * 64;

    const __half2* hl_src = (const __half2*)(src_is_B ? g_hlinB : g_hlinA);
    __half2*       hl_dst = (__half2*)(src_is_B ? g_hlinA : g_hlinB);
    __half2*       hkeep  = (__half2*)(keep_sel ? g_h1 : g_h0);
    const __half*  Wp     = w_is_3 ? g_w3 : g_w2;

    for (int i = tid; i < 64 * 8; i += 256) {
        int r = i >> 3, c = i & 7;
        *(uint4*)&Ws[r * 72 + c * 8] = *(const uint4*)&Wp[r * 64 + c * 8];
    }

    float b0 = bias[lane * 2], b1 = bias[lane * 2 + 1];
#pragma unroll 1
    for (int i = 0; i < 8; i++) {
        int node = row0 + warp * 8 + i;
        int cn = (node < NN) ? node : NN - 1;
        __half2 v = agg_node(hl_src, cn, lane, b0, b1);
        *(__half2*)&Xs[(warp * 8 + i) * XS + lane * 2] = v;
        if (node < NN) hkeep[(size_t)node * 32 + lane] = v;
    }
    __syncthreads();

    // gemm 64x64: 8 warps, warp tile 16 rows x 32 cols
    int wm = (warp & 3) * 16, wn = (warp >> 2) * 32;
    float acc[4][4];
#pragma unroll
    for (int g = 0; g < 4; g++) { acc[g][0] = acc[g][1] = acc[g][2] = acc[g][3] = 0.f; }

    unsigned xb = smem_u32(Xs), wb = smem_u32(Ws);
    int arow = wm + ((lane >> 3) & 1) * 8 + (lane & 7);
    int acol8 = (lane >> 4) * 8;
    int brow8 = ((lane >> 3) & 1) * 8 + (lane & 7);

#pragma unroll
    for (int kk = 0; kk < 4; kk++) {
        unsigned a0, a1, a2, a3;
        ldm_x4(a0, a1, a2, a3, xb + (arow * XS + kk * 16 + acol8) * 2);
#pragma unroll
        for (int jn = 0; jn < 2; jn++) {
            unsigned b0r, b1r, b2r, b3r;
            ldm_x4_t(b0r, b1r, b2r, b3r,
                     wb + ((kk * 16 + brow8) * 72 + wn + jn * 16 + acol8) * 2);
            mma16816(acc[jn * 2 + 0], a0, a1, a2, a3, b0r, b1r);
            mma16816(acc[jn * 2 + 1], a0, a1, a2, a3, b2r, b3r);
        }
    }

    int g = lane >> 2, q = lane & 3;
#pragma unroll
    for (int gn = 0; gn < 4; gn++) {
        int r0 = row0 + wm + g, r1 = r0 + 8;
        int cidx = (wn >> 1) + gn * 4 + q;
        if (r0 < NN) hl_dst[(size_t)r0 * 32 + cidx] = __floats2half2_rn(acc[gn][0], acc[gn][1]);
        if (r1 < NN) hl_dst[(size_t)r1 * 32 + cidx] = __floats2half2_rn(acc[gn][2], acc[gn][3]);
    }
}

// ---------------- fused agg + final: agg(hlinA)->h2(smem only), JK gemm -> out ----------------
__global__ void __launch_bounds__(256) agg_final_kernel(const float* __restrict__ bias3,
                                                        const float* __restrict__ blin,
                                                        float* __restrict__ out) {
    constexpr int XS = 72;
    __shared__ __half Xs[64 * XS];
    __shared__ __half Ws[192 * 72];

    int tid = threadIdx.x, warp = tid >> 5, lane = tid & 31;
    int row0 = blockIdx.x * 64;

    for (int i = tid; i < 192 * 8; i += 256) {
        int r = i >> 3, c = i & 7;
        *(uint4*)&Ws[r * 72 + c * 8] = *(const uint4*)&g_wl[r * 64 + c * 8];
    }

    // aggregate h2 for this block's 64 nodes into Xs (never touches global)
    float b0 = bias3[lane * 2], b1 = bias3[lane * 2 + 1];
#pragma unroll 1
    for (int i = 0; i < 8; i++) {
        int node = row0 + warp * 8 + i;
        int cn = (node < NN) ? node : NN - 1;
        __half2 v = agg_node((const __half2*)g_hlinA, cn, lane, b0, b1);
        *(__half2*)&Xs[(warp * 8 + i) * XS + lane * 2] = v;
    }
    __syncthreads();

    int wm = (warp & 3) * 16, wn = (warp >> 2) * 32;
    float acc[4][4];
#pragma unroll
    for (int g = 0; g < 4; g++) { acc[g][0] = acc[g][1] = acc[g][2] = acc[g][3] = 0.f; }

    unsigned xb = smem_u32(Xs), wb = smem_u32(Ws);
    int arow = wm + ((lane >> 3) & 1) * 8 + (lane & 7);
    int acol8 = (lane >> 4) * 8;
    int brow8 = ((lane >> 3) & 1) * 8 + (lane & 7);

    // segment order: h2 (in smem now), then h0, then h1
#pragma unroll 1
    for (int seg = 0; seg < 3; seg++) {
        int l = (seg == 0) ? 2 : (seg - 1);   // weight segment index
        if (seg > 0) {
            const __half* H = (seg == 1) ? g_h0 : g_h1;
            __syncthreads();
            for (int i = tid; i < 64 * 8; i += 256) {
                int r = i >> 3, c = i & 7;
                int gr = row0 + r; if (gr >= NN) gr = NN - 1;
                *(uint4*)&Xs[r * XS + c * 8] = *(const uint4*)&H[(size_t)gr * 64 + c * 8];
            }
            __syncthreads();
        }
#pragma unroll
        for (int kk = 0; kk < 4; kk++) {
            unsigned a0, a1, a2, a3;
            ldm_x4(a0, a1, a2, a3, xb + (arow * XS + kk * 16 + acol8) * 2);
#pragma unroll
            for (int jn = 0; jn < 2; jn++) {
                unsigned b0r, b1r, b2r, b3r;
                ldm_x4_t(b0r, b1r, b2r, b3r,
                         wb + ((l * 64 + kk * 16 + brow8) * 72 + wn + jn * 16 + acol8) * 2);
                mma16816(acc[jn * 2 + 0], a0, a1, a2, a3, b0r, b1r);
                mma16816(acc[jn * 2 + 1], a0, a1, a2, a3, b2r, b3r);
            }
        }
    }

    int g = lane >> 2, q = lane & 3;
#pragma unroll
    for (int gn = 0; gn < 4; gn++) {
        int col = wn + gn * 8 + q * 2;
        if (col >= OUTD) continue;
        float bb0 = blin[col], bb1 = blin[col + 1];
        int r0 = row0 + wm + g, r1 = r0 + 8;
        if (r0 < NN) {
            float2 o; o.x = acc[gn][0] + bb0; o.y = acc[gn][1] + bb1;
            *(float2*)&out[(size_t)r0 * OUTD + col] = o;
        }
        if (r1 < NN) {
            float2 o; o.x = acc[gn][2] + bb0; o.y = acc[gn][3] + bb1;
            *(float2*)&out[(size_t)r1 * OUTD + col] = o;
        }
    }
}

// ---------------- launch (8 kernels, single stream) ----------------
extern "C" void kernel_launch(void* const* d_in, const int* in_sizes, int n_in,
                              void* d_out, int out_size) {
    const float* x    = (const float*)d_in[0];
    const int*   ei32 = (const int*)d_in[1];
    const float* ew   = (const float*)d_in[2];
    const float* W1 = (const float*)d_in[3];
    const float* b1 = (const float*)d_in[4];
    const float* W2 = (const float*)d_in[5];
    const float* b2 = (const float*)d_in[6];
    const float* W3 = (const float*)d_in[7];
    const float* b3 = (const float*)d_in[8];
    const float* Wl = (const float*)d_in[9];
    const float* bl = (const float*)d_in[10];
    float* out = (float*)d_out;

    prepw_zero_kernel<<<NBLK, 256>>>(W1, W2, W3, Wl, ei32);
    hist_kernel<<<HB, 256>>>(ei32);
    scan_kernel<<<NBLK, 256>>>();
    fill_kernel<<<HB, 256>>>(ei32, ew);

    gemm1_mma_kernel<<<GB, 128>>>(x);                    // x @ W1 -> hlinA
    agg_gemm_kernel<<<GB, 256>>>(0, b1, 0, 0);           // agg(A)->h0 ; h0 @ W2 -> hlinB
    agg_gemm_kernel<<<GB, 256>>>(1, b2, 1, 1);           // agg(B)->h1 ; h1 @ W3 -> hlinA
    agg_final_kernel<<<GB, 256>>>(b3, bl, out);          // agg(A)->h2(smem) ; JK -> out
}

// round 12
// speedup vs baseline: 1.0656x; 1.0656x over previous
#include <cuda_runtime.h>
#include <cuda_fp16.h>

#define NN   50000
#define EE   800000
#define HID  64
#define IND  128
#define OUTD 40
#define NBLK ((NN + 255) / 256)   // 196
#define GB   ((NN + 63) / 64)     // 782
#define HB   ((EE + 255) / 256)   // 3125
#define WTOT (IND*64 + HID*64 + HID*64 + 192*64)

// ---------------- device scratch ----------------
__device__ __half g_hlin[NN * HID];
__device__ __half g_h0[NN * HID];
__device__ __half g_h1[NN * HID];
__device__ __half g_h2[NN * HID];
__device__ __half g_w1[IND * 64];
__device__ __half g_w2[HID * 64];
__device__ __half g_w3[HID * 64];
__device__ __half g_wl[192 * 64];
__device__ int   g_rowptr[NN + 1];
__device__ int   g_cnt[NN];
__device__ int   g_rank[EE];
__device__ int   g_agg[NBLK];
__device__ int   g_flag[NBLK];
__device__ int4  g_edge4[EE / 2];
__device__ int   g_is64;

__device__ __forceinline__ const __half* hsel(int s) {
    switch (s) {
        case 1:  return g_h0;
        case 2:  return g_h1;
        default: return g_h2;
    }
}
__device__ __forceinline__ __half* hdst(int s) {
    switch (s) {
        case 1:  return g_h0;
        case 2:  return g_h1;
        default: return g_h2;
    }
}
__device__ __forceinline__ const __half* wsel(int s) {
    switch (s) {
        case 1:  return g_w1;
        case 2:  return g_w2;
        default: return g_w3;
    }
}

__device__ __forceinline__ int clampN(int v) {
    return (v < 0) ? 0 : ((v >= NN) ? NN - 1 : v);
}
__device__ __forceinline__ int edge_at(const int* __restrict__ p32, int row, int e, int is64) {
    long long idx = (long long)row * EE + e;
    return is64 ? p32[2 * idx] : p32[idx];
}
__device__ __forceinline__ unsigned smem_u32(const void* p) {
    return (unsigned)__cvta_generic_to_shared(p);
}
__device__ __forceinline__ void ldm_x4(unsigned& r0, unsigned& r1, unsigned& r2, unsigned& r3, unsigned a) {
    asm volatile("ldmatrix.sync.aligned.m8n8.x4.shared.b16 {%0,%1,%2,%3}, [%4];"
                 : "=r"(r0), "=r"(r1), "=r"(r2), "=r"(r3) : "r"(a));
}
__device__ __forceinline__ void ldm_x4_t(unsigned& r0, unsigned& r1, unsigned& r2, unsigned& r3, unsigned a) {
    asm volatile("ldmatrix.sync.aligned.m8n8.x4.trans.shared.b16 {%0,%1,%2,%3}, [%4];"
                 : "=r"(r0), "=r"(r1), "=r"(r2), "=r"(r3) : "r"(a));
}
__device__ __forceinline__ void mma16816(float* c, unsigned a0, unsigned a1, unsigned a2, unsigned a3,
                                         unsigned b0, unsigned b1) {
    asm volatile("mma.sync.aligned.m16n8k16.row.col.f32.f16.f16.f32 "
                 "{%0,%1,%2,%3}, {%4,%5,%6,%7}, {%8,%9}, {%0,%1,%2,%3};"
                 : "+f"(c[0]), "+f"(c[1]), "+f"(c[2]), "+f"(c[3])
                 : "r"(a0), "r"(a1), "r"(a2), "r"(a3), "r"(b0), "r"(b1));
}

// ---------------- prep: weights fp32->fp16, zero counters/flags, dtype detect ----------------
__global__ void prepw_zero_kernel(const float* __restrict__ W1,
                                  const float* __restrict__ W2,
                                  const float* __restrict__ W3,
                                  const float* __restrict__ Wl,
                                  const int* __restrict__ p32) {
    int i = blockIdx.x * 256 + threadIdx.x;
    if (i < NN) g_cnt[i] = 0;
    if (i < NBLK) g_flag[i] = 0;
    if (i < WTOT) {
        int j = i;
        if (j < IND * 64) { g_w1[j] = __float2half_rn(W1[j]); }
        else {
            j -= IND * 64;
            if (j < HID * 64) { g_w2[j] = __float2half_rn(W2[j]); }
            else {
                j -= HID * 64;
                if (j < HID * 64) { g_w3[j] = __float2half_rn(W3[j]); }
                else {
                    j -= HID * 64;
                    int k = j >> 6, c = j & 63;
                    g_wl[j] = (c < OUTD) ? __float2half_rn(Wl[k * OUTD + c]) : __float2half_rn(0.f);
                }
            }
        }
    }
    if (blockIdx.x == 0 && threadIdx.x < 32) {
        int lane = threadIdx.x;
        int any = p32[2 * lane + 1] | p32[2 * (lane + 32) + 1];
        unsigned nz = __ballot_sync(0xFFFFFFFFu, any != 0);
        if (lane == 0) g_is64 = (nz == 0) ? 1 : 0;
    }
}

// ---------------- histogram + rank capture ----------------
__global__ void hist_kernel(const int* __restrict__ ei32) {
    int e = blockIdx.x * blockDim.x + threadIdx.x;
    if (e < EE) {
        int d = clampN(edge_at(ei32, 1, e, g_is64));
        g_rank[e] = atomicAdd(&g_cnt[d], 1);
    }
}

// ---------------- single-pass scan ----------------
__device__ __forceinline__ int block_excl_scan_256(int v, int tid, int* wsum) {
    int lane = tid & 31, w = tid >> 5;
    int x = v;
#pragma unroll
    for (int o = 1; o < 32; o <<= 1) {
        int y = __shfl_up_sync(0xFFFFFFFFu, x, o);
        if (lane >= o) x += y;
    }
    if (lane == 31) wsum[w] = x;
    __syncthreads();
    if (w == 0) {
        int s = (lane < 8) ? wsum[lane] : 0;
#pragma unroll
        for (int o = 1; o < 8; o <<= 1) {
            int y = __shfl_up_sync(0xFFFFFFFFu, s, o);
            if (lane >= o) s += y;
        }
        if (lane < 8) wsum[lane] = s;
    }
    __syncthreads();
    int incl = x + ((w > 0) ? wsum[w - 1] : 0);
    return incl - v;
}

__global__ void __launch_bounds__(256) scan_kernel() {
    __shared__ int wsum[8];
    __shared__ int s_off;
    int tid = threadIdx.x, b = blockIdx.x;

    int i = b * 256 + tid;
    int c = (i < NN) ? g_cnt[i] : 0;
    int excl = block_excl_scan_256(c, tid, wsum);
    int total = wsum[7];

    if (tid == 0) {
        g_agg[b] = total;
        __threadfence();
        *(volatile int*)&g_flag[b] = 1;
    }
    if (tid < 32) {
        int sum = 0;
        for (int p = tid; p < b; p += 32) {
            while (*(volatile int*)&g_flag[p] == 0) { }
            sum += *(volatile int*)&g_agg[p];
        }
#pragma unroll
        for (int o = 16; o > 0; o >>= 1) sum += __shfl_down_sync(0xFFFFFFFFu, sum, o);
        if (tid == 0) s_off = sum;
    }
    __syncthreads();
    int off = s_off;

    if (i < NN) g_rowptr[i] = off + excl;
    if (b == NBLK - 1 && tid == 0) g_rowptr[NN] = off + total;
}

// ---------------- fill: atomic-free scatter using precomputed ranks ----------------
__global__ void fill_kernel(const int* __restrict__ ei32,
                            const float* __restrict__ ew) {
    int e = blockIdx.x * blockDim.x + threadIdx.x;
    if (e < EE) {
        int is64 = g_is64;
        int d = clampN(edge_at(ei32, 1, e, is64));
        int s = clampN(edge_at(ei32, 0, e, is64));
        int pos = g_rowptr[d] + g_rank[e];
        ((int2*)g_edge4)[pos] = make_int2(s, __float_as_int(ew[e]));
    }
}

// ---------------- gemm layer 1: x fp32 -> hlin (converts while staging) ----------------
__global__ void __launch_bounds__(128) gemm1_mma_kernel(const float* __restrict__ x) {
    constexpr int K = IND;
    constexpr int XS = K + 8;
    __shared__ __half Xs[64 * XS];
    __shared__ __half Ws[K * 72];

    int tid = threadIdx.x, warp = tid >> 5, lane = tid & 31;
    int row0 = blockIdx.x * 64;

    constexpr int NF4 = K / 4;
    for (int i = tid; i < 64 * NF4; i += 128) {
        int r = i / NF4, c = i % NF4;
        int gr = row0 + r; if (gr >= NN) gr = NN - 1;
        float4 v = *(const float4*)&x[(size_t)gr * K + c * 4];
        __half2 h01 = __floats2half2_rn(v.x, v.y);
        __half2 h23 = __floats2half2_rn(v.z, v.w);
        uint2 pk; pk.x = *(unsigned*)&h01; pk.y = *(unsigned*)&h23;
        *(uint2*)&Xs[r * XS + c * 4] = pk;
    }
    for (int i = tid; i < K * 8; i += 128) {
        int r = i >> 3, c = i & 7;
        *(uint4*)&Ws[r * 72 + c * 8] = *(const uint4*)&g_w1[r * 64 + c * 8];
    }
    __syncthreads();

    int wr = warp * 16;
    float acc[8][4];
#pragma unroll
    for (int g = 0; g < 8; g++) { acc[g][0] = acc[g][1] = acc[g][2] = acc[g][3] = 0.f; }

    unsigned xb = smem_u32(Xs), wb = smem_u32(Ws);
    int arow = wr + ((lane >> 3) & 1) * 8 + (lane & 7);
    int acol8 = (lane >> 4) * 8;
    int brow8 = ((lane >> 3) & 1) * 8 + (lane & 7);

#pragma unroll
    for (int kk = 0; kk < K / 16; kk++) {
        unsigned a0, a1, a2, a3;
        ldm_x4(a0, a1, a2, a3, xb + (arow * XS + kk * 16 + acol8) * 2);
#pragma unroll
        for (int jn = 0; jn < 4; jn++) {
            unsigned b0, b1, b2, b3;
            ldm_x4_t(b0, b1, b2, b3, wb + ((kk * 16 + brow8) * 72 + jn * 16 + acol8) * 2);
            mma16816(acc[jn * 2 + 0], a0, a1, a2, a3, b0, b1);
            mma16816(acc[jn * 2 + 1], a0, a1, a2, a3, b2, b3);
        }
    }

    __half2* hl = (__half2*)g_hlin;
    int g = lane >> 2, q = lane & 3;
#pragma unroll
    for (int gn = 0; gn < 8; gn++) {
        int r0 = row0 + wr + g, r1 = r0 + 8;
        int cidx = gn * 4 + q;
        if (r0 < NN) hl[(size_t)r0 * 32 + cidx] = __floats2half2_rn(acc[gn][0], acc[gn][1]);
        if (r1 < NN) hl[(size_t)r1 * 32 + cidx] = __floats2half2_rn(acc[gn][2], acc[gn][3]);
    }
}

// ---------------- aggregation: warp per node, 8-edge unroll (MLP 8) ----------------
__global__ void __launch_bounds__(256) agg_kernel(int dst_sel,
                                                  const float* __restrict__ bias) {
    int gw   = (blockIdx.x * 256 + threadIdx.x) >> 5;
    int lane = threadIdx.x & 31;
    if (gw >= NN) return;

    const __half2* hl = (const __half2*)g_hlin;
    const int2*    ed = (const int2*)g_edge4;
    __half2*       hout = (__half2*)hdst(dst_sel);

    int beg = g_rowptr[gw], end = g_rowptr[gw + 1];
    float a0 = 0.f, a1 = 0.f, c0 = 0.f, c1 = 0.f;

    int e = beg;
    if ((e & 1) && e < end) {           // parity peel -> int4 alignment
        int2 E = ed[e];
        float2 h = __half22float2(hl[(size_t)E.x * 32 + lane]);
        float w = __int_as_float(E.y);
        a0 = fmaf(w, h.x, a0); a1 = fmaf(w, h.y, a1);
        e++;
    }
    // 8-edge main loop: 4 independent int4 loads + 8 independent gathers in flight
    for (; e + 8 <= end; e += 8) {
        int p = e >> 1;
        int4 Ea = g_edge4[p];
        int4 Eb = g_edge4[p + 1];
        int4 Ec = g_edge4[p + 2];
        int4 Ed = g_edge4[p + 3];
        float2 h0 = __half22float2(hl[(size_t)Ea.x * 32 + lane]);
        float2 h1 = __half22float2(hl[(size_t)Ea.z * 32 + lane]);
        float2 h2 = __half22float2(hl[(size_t)Eb.x * 32 + lane]);
        float2 h3 = __half22float2(hl[(size_t)Eb.z * 32 + lane]);
        float2 h4 = __half22float2(hl[(size_t)Ec.x * 32 + lane]);
        float2 h5 = __half22float2(hl[(size_t)Ec.z * 32 + lane]);
        float2 h6 = __half22float2(hl[(size_t)Ed.x * 32 + lane]);
        float2 h7 = __half22float2(hl[(size_t)Ed.z * 32 + lane]);
        float w0 = __int_as_float(Ea.y), w1 = __int_as_float(Ea.w);
        float w2 = __int_as_float(Eb.y), w3 = __int_as_float(Eb.w);
        float w4 = __int_as_float(Ec.y), w5 = __int_as_float(Ec.w);
        float w6 = __int_as_float(Ed.y), w7 = __int_as_float(Ed.w);
        a0 = fmaf(w0, h0.x, a0); a1 = fmaf(w0, h0.y, a1);
        c0 = fmaf(w1, h1.x, c0); c1 = fmaf(w1, h1.y, c1);
        a0 = fmaf(w2, h2.x, a0); a1 = fmaf(w2, h2.y, a1);
        c0 = fmaf(w3, h3.x, c0); c1 = fmaf(w3, h3.y, c1);
        a0 = fmaf(w4, h4.x, a0); a1 = fmaf(w4, h4.y, a1);
        c0 = fmaf(w5, h5.x, c0); c1 = fmaf(w5, h5.y, c1);
        a0 = fmaf(w6, h6.x, a0); a1 = fmaf(w6, h6.y, a1);
        c0 = fmaf(w7, h7.x, c0); c1 = fmaf(w7, h7.y, c1);
    }
    if (e + 4 <= end) {
        int p = e >> 1;
        int4 Ea = g_edge4[p];
        int4 Eb = g_edge4[p + 1];
        float2 h0 = __half22float2(hl[(size_t)Ea.x * 32 + lane]);
        float2 h1 = __half22float2(hl[(size_t)Ea.z * 32 + lane]);
        float2 h2 = __half22float2(hl[(size_t)Eb.x * 32 + lane]);
        float2 h3 = __half22float2(hl[(size_t)Eb.z * 32 + lane]);
        float w0 = __int_as_float(Ea.y), w1 = __int_as_float(Ea.w);
        float w2 = __int_as_float(Eb.y), w3 = __int_as_float(Eb.w);
        a0 = fmaf(w0, h0.x, a0); a1 = fmaf(w0, h0.y, a1);
        c0 = fmaf(w1, h1.x, c0); c1 = fmaf(w1, h1.y, c1);
        a0 = fmaf(w2, h2.x, a0); a1 = fmaf(w2, h2.y, a1);
        c0 = fmaf(w3, h3.x, c0); c1 = fmaf(w3, h3.y, c1);
        e += 4;
    }
    if (e + 2 <= end) {
        int4 Ea = g_edge4[e >> 1];
        float2 h0 = __half22float2(hl[(size_t)Ea.x * 32 + lane]);
        float2 h1 = __half22float2(hl[(size_t)Ea.z * 32 + lane]);
        float w0 = __int_as_float(Ea.y), w1 = __int_as_float(Ea.w);
        a0 = fmaf(w0, h0.x, a0); a1 = fmaf(w0, h0.y, a1);
        c0 = fmaf(w1, h1.x, c0); c1 = fmaf(w1, h1.y, c1);
        e += 2;
    }
    if (e < end) {
        int2 E = ed[e];
        float2 h = __half22float2(hl[(size_t)E.x * 32 + lane]);
        float w = __int_as_float(E.y);
        a0 = fmaf(w, h.x, a0); a1 = fmaf(w, h.y, a1);
    }
    a0 += c0; a1 += c1;

    float b0 = bias[lane * 2], b1 = bias[lane * 2 + 1];
    hout[(size_t)gw * 32 + lane] =
        __floats2half2_rn(fmaxf(a0 + b0, 0.f), fmaxf(a1 + b1, 0.f));
}

// ---------------- gemm layers 2,3 (fp16 in/out) ----------------
__global__ void __launch_bounds__(128) gemm_mma_kernel(int src_sel, int w_sel) {
    constexpr int K = HID;
    constexpr int XS = K + 8;
    __shared__ __half Xs[64 * XS];
    __shared__ __half Ws[K * 72];

    int tid = threadIdx.x, warp = tid >> 5, lane = tid & 31;
    int row0 = blockIdx.x * 64;

    const __half* X = hsel(src_sel);
    const __half* Wp = wsel(w_sel);

    constexpr int NV = K / 8;
    for (int i = tid; i < 64 * NV; i += 128) {
        int r = i / NV, c = i % NV;
        int gr = row0 + r; if (gr >= NN) gr = NN - 1;
        *(uint4*)&Xs[r * XS + c * 8] = *(const uint4*)&X[(size_t)gr * K + c * 8];
    }
    for (int i = tid; i < K * 8; i += 128) {
        int r = i >> 3, c = i & 7;
        *(uint4*)&Ws[r * 72 + c * 8] = *(const uint4*)&Wp[r * 64 + c * 8];
    }
    __syncthreads();

    int wr = warp * 16;
    float acc[8][4];
#pragma unroll
    for (int g = 0; g < 8; g++) { acc[g][0] = acc[g][1] = acc[g][2] = acc[g][3] = 0.f; }

    unsigned xb = smem_u32(Xs), wb = smem_u32(Ws);
    int arow = wr + ((lane >> 3) & 1) * 8 + (lane & 7);
    int acol8 = (lane >> 4) * 8;
    int brow8 = ((lane >> 3) & 1) * 8 + (lane & 7);

#pragma unroll
    for (int kk = 0; kk < K / 16; kk++) {
        unsigned a0, a1, a2, a3;
        ldm_x4(a0, a1, a2, a3, xb + (arow * XS + kk * 16 + acol8) * 2);
#pragma unroll
        for (int jn = 0; jn < 4; jn++) {
            unsigned b0, b1, b2, b3;
            ldm_x4_t(b0, b1, b2, b3, wb + ((kk * 16 + brow8) * 72 + jn * 16 + acol8) * 2);
            mma16816(acc[jn * 2 + 0], a0, a1, a2, a3, b0, b1);
            mma16816(acc[jn * 2 + 1], a0, a1, a2, a3, b2, b3);
        }
    }

    __half2* hl = (__half2*)g_hlin;
    int g = lane >> 2, q = lane & 3;
#pragma unroll
    for (int gn = 0; gn < 8; gn++) {
        int r0 = row0 + wr + g, r1 = r0 + 8;
        int cidx = gn * 4 + q;
        if (r0 < NN) hl[(size_t)r0 * 32 + cidx] = __floats2half2_rn(acc[gn][0], acc[gn][1]);
        if (r1 < NN) hl[(size_t)r1 * 32 + cidx] = __floats2half2_rn(acc[gn][2], acc[gn][3]);
    }
}

// ---------------- final: out[N,40] = [h0|h1|h2] @ Wlin + blin ----------------
__global__ void __launch_bounds__(128) final_mma_kernel(const float* __restrict__ blin,
                                                        float* __restrict__ out) {
    constexpr int XS = 72;
    __shared__ __half Xs[64 * XS];
    __shared__ __half Ws[192 * 72];

    int tid = threadIdx.x, warp = tid >> 5, lane = tid & 31;
    int row0 = blockIdx.x * 64;

    for (int i = tid; i < 192 * 8; i += 128) {
        int r = i >> 3, c = i & 7;
        *(uint4*)&Ws[r * 72 + c * 8] = *(const uint4*)&g_wl[r * 64 + c * 8];
    }

    int wr = warp * 16;
    float acc[8][4];
#pragma unroll
    for (int g = 0; g < 8; g++) { acc[g][0] = acc[g][1] = acc[g][2] = acc[g][3] = 0.f; }

    unsigned xb = smem_u32(Xs), wb = smem_u32(Ws);
    int arow = wr + ((lane >> 3) & 1) * 8 + (lane & 7);
    int acol8 = (lane >> 4) * 8;
    int brow8 = ((lane >> 3) & 1) * 8 + (lane & 7);

#pragma unroll 1
    for (int l = 0; l < 3; l++) {
        const __half* H = hsel(1 + l);
        __syncthreads();
        for (int i = tid; i < 64 * 8; i += 128) {
            int r = i >> 3, c = i & 7;
            int gr = row0 + r; if (gr >= NN) gr = NN - 1;
            *(uint4*)&Xs[r * XS + c * 8] = *(const uint4*)&H[(size_t)gr * 64 + c * 8];
        }
        __syncthreads();

#pragma unroll
        for (int kk = 0; kk < 4; kk++) {
            unsigned a0, a1, a2, a3;
            ldm_x4(a0, a1, a2, a3, xb + (arow * XS + kk * 16 + acol8) * 2);
#pragma unroll
            for (int jn = 0; jn < 4; jn++) {
                unsigned b0, b1, b2, b3;
                ldm_x4_t(b0, b1, b2, b3,
                         wb + ((l * 64 + kk * 16 + brow8) * 72 + jn * 16 + acol8) * 2);
                mma16816(acc[jn * 2 + 0], a0, a1, a2, a3, b0, b1);
                mma16816(acc[jn * 2 + 1], a0, a1, a2, a3, b2, b3);
            }
        }
    }

    int g = lane >> 2, q = lane & 3;
#pragma unroll
    for (int gn = 0; gn < 5; gn++) {
        int col = gn * 8 + q * 2;
        if (col >= OUTD) continue;
        float b0 = blin[col], b1 = blin[col + 1];
        int r0 = row0 + wr + g, r1 = r0 + 8;
        if (r0 < NN) {
            float2 o; o.x = acc[gn][0] + b0; o.y = acc[gn][1] + b1;
            *(float2*)&out[(size_t)r0 * OUTD + col] = o;
        }
        if (r1 < NN) {
            float2 o; o.x = acc[gn][2] + b0; o.y = acc[gn][3] + b1;
            *(float2*)&out[(size_t)r1 * OUTD + col] = o;
        }
    }
}

// ---------------- launch (11 kernels, single stream) ----------------
extern "C" void kernel_launch(void* const* d_in, const int* in_sizes, int n_in,
                              void* d_out, int out_size) {
    const float* x    = (const float*)d_in[0];
    const int*   ei32 = (const int*)d_in[1];
    const float* ew   = (const float*)d_in[2];
    const float* W1 = (const float*)d_in[3];
    const float* b1 = (const float*)d_in[4];
    const float* W2 = (const float*)d_in[5];
    const float* b2 = (const float*)d_in[6];
    const float* W3 = (const float*)d_in[7];
    const float* b3 = (const float*)d_in[8];
    const float* Wl = (const float*)d_in[9];
    const float* bl = (const float*)d_in[10];
    float* out = (float*)d_out;

    const int AB = (NN * 32 + 255) / 256;     // 6250

    prepw_zero_kernel<<<NBLK, 256>>>(W1, W2, W3, Wl, ei32);   // 0
    hist_kernel<<<HB, 256>>>(ei32);                           // 1
    scan_kernel<<<NBLK, 256>>>();                             // 2
    fill_kernel<<<HB, 256>>>(ei32, ew);                       // 3
    gemm1_mma_kernel<<<GB, 128>>>(x);                         // 4
    agg_kernel<<<AB, 256>>>(1, b1);                           // 5 <- ncu profiles this
    gemm_mma_kernel<<<GB, 128>>>(1, 2);                       // 6
    agg_kernel<<<AB, 256>>>(2, b2);                           // 7
    gemm_mma_kernel<<<GB, 128>>>(2, 3);                       // 8
    agg_kernel<<<AB, 256>>>(3, b3);                           // 9
    final_mma_kernel<<<GB, 128>>>(bl, out);                   // 10
}